// round 2
// baseline (speedup 1.0000x reference)
#include <cuda_runtime.h>
#include <cuda_fp16.h>
#include <cstdint>

// out[8192,4096] = x[8192,4096] @ W[4096,4096]^T,  W = (q - zp)*scale
// Path: prep x->fp16, (q-zp)->fp16 (both exact enough); fp16 HMMA GEMM with
// fp32 accumulation via mma.sync.m16n8k16 (legacy tensor path — tcgen05 is
// unavailable because the harness targets virtual compute_103, non-'a').
#define MDIM 8192
#define KDIM 4096
#define NDIM 4096

// device scratch (allocation-free)
__device__ __half g_xh[(size_t)MDIM * KDIM];   // 64 MB
__device__ __half g_wh[(size_t)NDIM * KDIM];   // 32 MB

__device__ __forceinline__ uint32_t smem_to_u32(const void* p) {
    uint32_t a;
    asm("{ .reg .u64 t; cvta.to.shared.u64 t, %1; cvt.u32.u64 %0, t; }"
        : "=r"(a) : "l"(p));
    return a;
}

#define CP_ASYNC16(smem_u32, gptr) \
    asm volatile("cp.async.cg.shared.global [%0], [%1], 16;\n" \
        :: "r"(smem_u32), "l"(gptr) : "memory")
#define CP_ASYNC_COMMIT() asm volatile("cp.async.commit_group;\n" ::: "memory")
#define CP_ASYNC_WAIT2()  asm volatile("cp.async.wait_group 2;\n" ::: "memory")
#define CP_ASYNC_WAIT0()  asm volatile("cp.async.wait_group 0;\n" ::: "memory")

#define LDMATRIX_X4(r0, r1, r2, r3, addr) \
    asm volatile("ldmatrix.sync.aligned.m8n8.x4.shared.b16 {%0,%1,%2,%3}, [%4];" \
        : "=r"(r0), "=r"(r1), "=r"(r2), "=r"(r3) : "r"(addr))

#define MMA_16816(c, a0, a1, a2, a3, b0, b1) \
    asm volatile("mma.sync.aligned.m16n8k16.row.col.f32.f16.f16.f32 " \
        "{%0,%1,%2,%3}, {%4,%5,%6,%7}, {%8,%9}, {%0,%1,%2,%3};" \
        : "+f"((c)[0]), "+f"((c)[1]), "+f"((c)[2]), "+f"((c)[3]) \
        : "r"(a0), "r"(a1), "r"(a2), "r"(a3), "r"(b0), "r"(b1))

// ------------------------------- prep kernels ------------------------------
__global__ void __launch_bounds__(256) split_x_kernel(const float* __restrict__ x) {
    size_t i = (size_t)blockIdx.x * blockDim.x + threadIdx.x;   // float4 index
    float4 v = reinterpret_cast<const float4*>(x)[i];
    __half2 lo = __floats2half2_rn(v.x, v.y);
    __half2 hi = __floats2half2_rn(v.z, v.w);
    uint2 o;
    o.x = *reinterpret_cast<uint32_t*>(&lo);
    o.y = *reinterpret_cast<uint32_t*>(&hi);
    reinterpret_cast<uint2*>(g_xh)[i] = o;
}

__global__ void __launch_bounds__(256) prep_w_kernel(const int* __restrict__ q,
                                                     const int* __restrict__ zp) {
    int z = zp[0];
    size_t i = (size_t)blockIdx.x * blockDim.x + threadIdx.x;   // int4 index
    int4 qq = reinterpret_cast<const int4*>(q)[i];
    __half2 lo = __floats2half2_rn((float)(qq.x - z), (float)(qq.y - z));
    __half2 hi = __floats2half2_rn((float)(qq.z - z), (float)(qq.w - z));
    uint2 o;
    o.x = *reinterpret_cast<uint32_t*>(&lo);
    o.y = *reinterpret_cast<uint32_t*>(&hi);
    reinterpret_cast<uint2*>(g_wh)[i] = o;
}

// ------------------------------- GEMM --------------------------------------
// CTA tile 128x128, K-chunk 32 (fp16). 8 warps: 2 (M) x 4 (N), warp tile 64x32.
// SMEM: padded rows of 80B (32 halves + 8 pad) for conflict-free ldmatrix.
static constexpr int BM = 128, BN = 128, BK = 32;
static constexpr int LDS = 80;                       // bytes per SMEM row
static constexpr int A_BYTES = BM * LDS;             // 10240
static constexpr int STAGE_BYTES = 2 * A_BYTES;      // 20480 (A then B)
static constexpr int STAGES = 4;
static constexpr int SMEM_TOTAL = STAGES * STAGE_BYTES;  // 81920
static constexpr int KT = KDIM / BK;                 // 128

__global__ void __launch_bounds__(256, 1)
gemm_kernel(const float* __restrict__ bias,
            const float* __restrict__ wscale,
            float* __restrict__ out) {
    extern __shared__ char smem[];
    const uint32_t sbase = smem_to_u32(smem);
    const int tid = threadIdx.x;
    const int lane = tid & 31;
    const int wid = tid >> 5;
    const int warp_m = wid & 1;        // 0..1
    const int warp_n = wid >> 1;       // 0..3

    // CTA swizzle: groups of 8 M-blocks sweep all N-blocks -> W reuse in L2
    const int NBLK = NDIM / BN;        // 32
    const int G = 8;
    int bid = blockIdx.x;
    int grp = bid / (G * NBLK);
    int rr = bid % (G * NBLK);
    const int m0 = (grp * G + (rr % G)) * BM;
    const int n0 = (rr / G) * BN;

    // cp.async stage loader: thread covers 2 A-chunks + 2 B-chunks of 16B
    auto load_stage = [&](int kt, int s) {
        const uint32_t st = sbase + s * STAGE_BYTES;
        const int k0 = kt * BK;
        #pragma unroll
        for (int i = 0; i < 2; i++) {
            int idx = tid * 2 + i;            // 0..511
            int row = idx >> 2, ch = idx & 3; // 16B chunk within 64B of data
            const __half* ga = g_xh + (size_t)(m0 + row) * KDIM + k0 + ch * 8;
            const __half* gb = g_wh + (size_t)(n0 + row) * KDIM + k0 + ch * 8;
            CP_ASYNC16(st + row * LDS + ch * 16, ga);
            CP_ASYNC16(st + A_BYTES + row * LDS + ch * 16, gb);
        }
    };

    // per-lane ldmatrix address components (shared by A and B):
    // address groups: [rows0-7,k0-7][rows8-15,k0-7][rows0-7,k8-15][rows8-15,k8-15]
    const int rin = ((lane >> 3) & 1) * 8 + (lane & 7);
    const int khb = (lane >> 4) * 16;     // byte offset for k-half

    const uint32_t aLane = (uint32_t)((warp_m * 64 + rin) * LDS + khb);
    const uint32_t bLane = (uint32_t)(A_BYTES + (warp_n * 32 + rin) * LDS + khb);

    float acc[4][4][4];
    #pragma unroll
    for (int i = 0; i < 4; i++)
        #pragma unroll
        for (int j = 0; j < 4; j++)
            #pragma unroll
            for (int k = 0; k < 4; k++) acc[i][j][k] = 0.f;

    load_stage(0, 0); CP_ASYNC_COMMIT();
    load_stage(1, 1); CP_ASYNC_COMMIT();
    load_stage(2, 2); CP_ASYNC_COMMIT();

    #pragma unroll 1
    for (int kt = 0; kt < KT; kt++) {
        CP_ASYNC_WAIT2();
        __syncthreads();
        const uint32_t so = sbase + (kt & 3) * STAGE_BYTES;

        #pragma unroll
        for (int ks = 0; ks < 2; ks++) {
            uint32_t a[4][4], b[2][4];
            #pragma unroll
            for (int mi = 0; mi < 4; mi++) {
                uint32_t ad = so + aLane + mi * (16 * LDS) + ks * 32;
                LDMATRIX_X4(a[mi][0], a[mi][1], a[mi][2], a[mi][3], ad);
            }
            #pragma unroll
            for (int np = 0; np < 2; np++) {
                uint32_t bd = so + bLane + np * (16 * LDS) + ks * 32;
                LDMATRIX_X4(b[np][0], b[np][1], b[np][2], b[np][3], bd);
            }
            if (ks == 0) {  // overlap next-stage issue with compute
                if (kt + 3 < KT) load_stage(kt + 3, (kt + 3) & 3);
                CP_ASYNC_COMMIT();
            }
            #pragma unroll
            for (int mi = 0; mi < 4; mi++)
                #pragma unroll
                for (int ni = 0; ni < 4; ni++) {
                    int pr = ni >> 1, tile = ni & 1;
                    MMA_16816(acc[mi][ni],
                              a[mi][0], a[mi][1], a[mi][2], a[mi][3],
                              b[pr][tile], b[pr][tile + 2]);
                }
        }
    }
    CP_ASYNC_WAIT0();

    // epilogue: scale + bias, direct float2 stores (coalesced in 8 B pairs)
    const float scale = __ldg(wscale);
    const int g = lane >> 2, tg = lane & 3;
    #pragma unroll
    for (int mi = 0; mi < 4; mi++) {
        #pragma unroll
        for (int ni = 0; ni < 4; ni++) {
            int col = n0 + warp_n * 32 + ni * 8 + tg * 2;
            float2 bb = *reinterpret_cast<const float2*>(bias + col);
            #pragma unroll
            for (int rh = 0; rh < 2; rh++) {
                int row = m0 + warp_m * 64 + mi * 16 + g + rh * 8;
                float2 v;
                v.x = acc[mi][ni][rh * 2 + 0] * scale + bb.x;
                v.y = acc[mi][ni][rh * 2 + 1] * scale + bb.y;
                *reinterpret_cast<float2*>(out + (size_t)row * NDIM + col) = v;
            }
        }
    }
}

// ------------------------------- launch ------------------------------------
extern "C" void kernel_launch(void* const* d_in, const int* in_sizes, int n_in,
                              void* d_out, int out_size) {
    const float* x     = (const float*)d_in[0];
    const int*   q     = (const int*)d_in[1];
    const int*   zp    = (const int*)d_in[2];
    const float* scale = (const float*)d_in[3];
    const float* bias  = (const float*)d_in[4];
    float* out = (float*)d_out;

    cudaFuncSetAttribute(gemm_kernel, cudaFuncAttributeMaxDynamicSharedMemorySize, SMEM_TOTAL);

    split_x_kernel<<<(int)(((size_t)MDIM * KDIM / 4) / 256), 256>>>(x);
    prep_w_kernel<<<(int)(((size_t)NDIM * KDIM / 4) / 256), 256>>>(q, zp);

    const int grid = (MDIM / BM) * (NDIM / BN);   // 64 * 32 = 2048
    gemm_kernel<<<grid, 256, SMEM_TOTAL>>>(bias, scale, out);
}

// round 3
// speedup vs baseline: 1.2639x; 1.2639x over previous
#include <cuda_runtime.h>
#include <cuda_fp16.h>
#include <cstdint>

// out[8192,4096] = x[8192,4096] @ W[4096,4096]^T,  W = (q - zp)*scale
// fp16 HMMA (mma.sync.m16n8k16, fp32 accum). Loads via cp.async.bulk (sm_90
// baseline) from prep-tiled, pre-swizzled scratch -> near-zero load issue cost.
#define MDIM 8192
#define KDIM 4096
#define NDIM 4096

static constexpr int BM = 128, BN = 256, BK = 32;
static constexpr int A_BLK = BM * BK * 2;     // 8192 B per (m-tile, k-chunk)
static constexpr int B_BLK = BN * BK * 2;     // 16384 B
static constexpr int STAGE = A_BLK + B_BLK;   // 24576
static constexpr int ST = 4;
static constexpr int KT = KDIM / BK;          // 128
static constexpr int SMEM_TOTAL = 1024 + ST * STAGE;  // 99328

// tiled+swizzled scratch: A: [64 m-tiles][128 kt][8KB], B: [16 n-tiles][128 kt][16KB]
__device__ uint4 g_xa[(size_t)MDIM * KDIM * 2 / 16];
__device__ uint4 g_wb[(size_t)NDIM * KDIM * 2 / 16];

__device__ __forceinline__ uint32_t smem_to_u32(const void* p) {
    uint32_t a;
    asm("{ .reg .u64 t; cvta.to.shared.u64 t, %1; cvt.u32.u64 %0, t; }"
        : "=r"(a) : "l"(p));
    return a;
}

#define MBARRIER_INIT(addr, cnt) \
    asm volatile("mbarrier.init.shared.b64 [%0], %1;" :: "r"((uint32_t)(addr)), "r"((uint32_t)(cnt)) : "memory")
#define MBARRIER_ARRIVE(addr) \
    asm volatile("mbarrier.arrive.shared.b64 _, [%0];" :: "r"((uint32_t)(addr)) : "memory")
#define MBARRIER_EXPECT_TX(addr, bytes) \
    asm volatile("mbarrier.arrive.expect_tx.shared.b64 _, [%0], %1;" :: "r"((uint32_t)(addr)), "r"((uint32_t)(bytes)) : "memory")
#define MBARRIER_WAIT_PARITY(mbar_smem_addr, phase_parity) do { \
    uint32_t _mbar = (uint32_t)(mbar_smem_addr); \
    uint32_t _parity = (uint32_t)(phase_parity); \
    uint32_t _done; \
    asm volatile( \
        "{\n\t.reg .pred p;\n\t" \
        "mbarrier.try_wait.parity.acquire.cta.shared::cta.b64 p, [%1], %2;\n\t" \
        "selp.b32 %0, 1, 0, p;\n\t}" \
        : "=r"(_done) : "r"(_mbar), "r"(_parity) : "memory"); \
    if (!_done) { \
        asm volatile( \
            "{\n\t.reg .pred P1;\n\t" \
            "WAIT_LOOP_%=:\n\t" \
            "mbarrier.try_wait.parity.acquire.cta.shared::cta.b64 P1, [%0], %1, 0x989680;\n\t" \
            "@P1 bra.uni WAIT_DONE_%=;\n\t" \
            "bra.uni WAIT_LOOP_%=;\n\t" \
            "WAIT_DONE_%=:\n\t}" \
            :: "r"(_mbar), "r"(_parity) : "memory"); \
    } \
} while(0)

#define BULK_G2S(dst, src, bytes, mbar) \
    asm volatile("cp.async.bulk.shared::cluster.global.mbarrier::complete_tx::bytes [%0], [%1], %2, [%3];" \
        :: "r"((uint32_t)(dst)), "l"(src), "r"((uint32_t)(bytes)), "r"((uint32_t)(mbar)) : "memory")

#define LDMATRIX_X4(r0, r1, r2, r3, addr) \
    asm volatile("ldmatrix.sync.aligned.m8n8.x4.shared.b16 {%0,%1,%2,%3}, [%4];" \
        : "=r"(r0), "=r"(r1), "=r"(r2), "=r"(r3) : "r"(addr))

#define MMA_16816(c, a0, a1, a2, a3, b0, b1) \
    asm volatile("mma.sync.aligned.m16n8k16.row.col.f32.f16.f16.f32 " \
        "{%0,%1,%2,%3}, {%4,%5,%6,%7}, {%8,%9}, {%0,%1,%2,%3};" \
        : "+f"((c)[0]), "+f"((c)[1]), "+f"((c)[2]), "+f"((c)[3]) \
        : "r"(a0), "r"(a1), "r"(a2), "r"(a3), "r"(b0), "r"(b1))

// ------------------------------- prep kernels ------------------------------
// Pack fp16 values into the tiled+swizzled layout the GEMM bulk-copies from.
// Within an 8KB/16KB block: element (r, kc): byte off = r*64 + kc*2;
// 16B unit index (bits 4-6) gets XORed with (r>>1)&7 -> ldmatrix conflict-free.
__device__ __forceinline__ uint32_t swz_off(int r, int kc8) {
    uint32_t unit = (uint32_t)(((r & 1) * 4 + kc8) ^ ((r >> 1) & 7));
    return (uint32_t)((r >> 1) * 128) + unit * 16;
}

__global__ void __launch_bounds__(256) prep_x_kernel(const float* __restrict__ x) {
    size_t t = (size_t)blockIdx.x * blockDim.x + threadIdx.x;  // one 16B out unit
    int m = (int)(t >> 9);              // 4096/8 = 512 units per row
    int k = ((int)t & 511) * 8;
    const float4* src = reinterpret_cast<const float4*>(x + (size_t)m * KDIM + k);
    float4 v0 = src[0], v1 = src[1];
    __half2 h0 = __floats2half2_rn(v0.x, v0.y);
    __half2 h1 = __floats2half2_rn(v0.z, v0.w);
    __half2 h2 = __floats2half2_rn(v1.x, v1.y);
    __half2 h3 = __floats2half2_rn(v1.z, v1.w);
    uint4 o;
    o.x = *reinterpret_cast<uint32_t*>(&h0);
    o.y = *reinterpret_cast<uint32_t*>(&h1);
    o.z = *reinterpret_cast<uint32_t*>(&h2);
    o.w = *reinterpret_cast<uint32_t*>(&h3);
    int mt = m >> 7, r = m & 127, kt = k >> 5, kc8 = (k & 31) >> 3;
    size_t dst = ((size_t)(mt * KT + kt) * A_BLK + swz_off(r, kc8)) >> 4;
    g_xa[dst] = o;
}

__global__ void __launch_bounds__(256) prep_w_kernel(const int* __restrict__ q,
                                                     const int* __restrict__ zp) {
    int z = __ldg(zp);
    size_t t = (size_t)blockIdx.x * blockDim.x + threadIdx.x;
    int n = (int)(t >> 9);
    int k = ((int)t & 511) * 8;
    const int4* src = reinterpret_cast<const int4*>(q + (size_t)n * KDIM + k);
    int4 q0 = src[0], q1 = src[1];
    __half2 h0 = __floats2half2_rn((float)(q0.x - z), (float)(q0.y - z));
    __half2 h1 = __floats2half2_rn((float)(q0.z - z), (float)(q0.w - z));
    __half2 h2 = __floats2half2_rn((float)(q1.x - z), (float)(q1.y - z));
    __half2 h3 = __floats2half2_rn((float)(q1.z - z), (float)(q1.w - z));
    uint4 o;
    o.x = *reinterpret_cast<uint32_t*>(&h0);
    o.y = *reinterpret_cast<uint32_t*>(&h1);
    o.z = *reinterpret_cast<uint32_t*>(&h2);
    o.w = *reinterpret_cast<uint32_t*>(&h3);
    int nt = n >> 8, r = n & 255, kt = k >> 5, kc8 = (k & 31) >> 3;
    size_t dst = ((size_t)(nt * KT + kt) * B_BLK + swz_off(r, kc8)) >> 4;
    g_wb[dst] = o;
}

// ------------------------------- GEMM --------------------------------------
// CTA 128x256, K-chunk 32. 8 warps: 2(M) x 4(N), warp tile 64x64.
__global__ void __launch_bounds__(256, 1)
gemm_kernel(const float* __restrict__ bias,
            const float* __restrict__ wscale,
            float* __restrict__ out) {
    extern __shared__ char smem[];
    const uint32_t sbase = smem_to_u32(smem);
    const int tid = threadIdx.x;
    const int lane = tid & 31;
    const int wid = tid >> 5;
    const int warp_m = wid & 1;
    const int warp_n = wid >> 1;

    // CTA swizzle: groups of 8 M-tiles sweep all 16 N-tiles (W + x reuse in L2)
    const int NBLK = NDIM / BN;   // 16
    int bid = blockIdx.x;
    int grp = bid >> 7;           // / (8*16)
    int rr = bid & 127;
    const int mt = grp * 8 + (rr & 7);
    const int nt = rr >> 3;
    const int m0 = mt * BM, n0 = nt * BN;

    // barriers: full[s] at sbase+16*s, empty[s] at sbase+128+16*s
    const uint32_t fullb = sbase, emptyb = sbase + 128;
    if (tid == 0) {
        #pragma unroll
        for (int s = 0; s < ST; s++) {
            MBARRIER_INIT(fullb + 16 * s, 1);
            MBARRIER_INIT(emptyb + 16 * s, 8);
        }
    }
    __syncthreads();

    const char* srcA = (const char*)g_xa + (size_t)mt * KT * A_BLK;
    const char* srcB = (const char*)g_wb + (size_t)nt * KT * B_BLK;

    // prologue: stages 0..2
    if (tid == 0) {
        #pragma unroll
        for (int j = 0; j < 3; j++) {
            MBARRIER_EXPECT_TX(fullb + 16 * j, STAGE);
            BULK_G2S(sbase + 1024 + j * STAGE, srcA + (size_t)j * A_BLK, A_BLK, fullb + 16 * j);
            BULK_G2S(sbase + 1024 + j * STAGE + A_BLK, srcB + (size_t)j * B_BLK, B_BLK, fullb + 16 * j);
        }
    }

    // per-lane ldmatrix offsets (same for A and B blocks)
    const int rin = ((lane >> 3) & 1) * 8 + (lane & 7);   // 0..15
    const int kh = lane >> 4;                              // k-half
    const int xr = (rin >> 1) & 7;
    const int rb = (rin >> 1) * 128;
    const uint32_t off_ks0 = (uint32_t)(rb + ((((rin & 1) * 4) + kh) ^ xr) * 16);
    const uint32_t off_ks1 = (uint32_t)(rb + ((((rin & 1) * 4) + 2 + kh) ^ xr) * 16);
    const uint32_t aW = (uint32_t)(warp_m * 4096);         // 64 rows * 64B
    const uint32_t bW = (uint32_t)(A_BLK + warp_n * 4096);

    float acc[4][8][4];
    #pragma unroll
    for (int i = 0; i < 4; i++)
        #pragma unroll
        for (int j = 0; j < 8; j++)
            #pragma unroll
            for (int c = 0; c < 4; c++) acc[i][j][c] = 0.f;

    #pragma unroll 1
    for (int kt = 0; kt < KT; kt++) {
        const int s = kt & 3;
        // producer: issue chunk kt+3 into stage (kt+3)&3
        if (tid == 0) {
            int j = kt + 3;
            if (j < KT) {
                int sj = j & 3;
                if (kt >= 1) MBARRIER_WAIT_PARITY(emptyb + 16 * sj, ((kt - 1) >> 2) & 1);
                MBARRIER_EXPECT_TX(fullb + 16 * sj, STAGE);
                BULK_G2S(sbase + 1024 + sj * STAGE, srcA + (size_t)j * A_BLK, A_BLK, fullb + 16 * sj);
                BULK_G2S(sbase + 1024 + sj * STAGE + A_BLK, srcB + (size_t)j * B_BLK, B_BLK, fullb + 16 * sj);
            }
        }
        MBARRIER_WAIT_PARITY(fullb + 16 * s, (kt >> 2) & 1);
        const uint32_t sa = sbase + 1024 + s * STAGE;

        #pragma unroll
        for (int ks = 0; ks < 2; ks++) {
            const uint32_t lo = ks ? off_ks1 : off_ks0;
            uint32_t a[4][4], b[4][4];
            #pragma unroll
            for (int mi = 0; mi < 4; mi++)
                LDMATRIX_X4(a[mi][0], a[mi][1], a[mi][2], a[mi][3],
                            sa + aW + mi * 1024 + lo);
            #pragma unroll
            for (int nj = 0; nj < 4; nj++)
                LDMATRIX_X4(b[nj][0], b[nj][1], b[nj][2], b[nj][3],
                            sa + bW + nj * 1024 + lo);
            #pragma unroll
            for (int mi = 0; mi < 4; mi++)
                #pragma unroll
                for (int v = 0; v < 8; v++) {
                    int nj = v >> 1, tb = v & 1;
                    MMA_16816(acc[mi][v],
                              a[mi][0], a[mi][1], a[mi][2], a[mi][3],
                              b[nj][tb], b[nj][tb + 2]);
                }
        }
        if (lane == 0) MBARRIER_ARRIVE(emptyb + 16 * s);
    }

    // epilogue: scale + bias, float2 stores
    const float scale = __ldg(wscale);
    const int g = lane >> 2, tg = lane & 3;
    #pragma unroll
    for (int mi = 0; mi < 4; mi++) {
        #pragma unroll
        for (int v = 0; v < 8; v++) {
            int col = n0 + warp_n * 64 + v * 8 + tg * 2;
            float2 bb = *reinterpret_cast<const float2*>(bias + col);
            #pragma unroll
            for (int rh = 0; rh < 2; rh++) {
                int row = m0 + warp_m * 64 + mi * 16 + g + rh * 8;
                float2 o;
                o.x = acc[mi][v][rh * 2 + 0] * scale + bb.x;
                o.y = acc[mi][v][rh * 2 + 1] * scale + bb.y;
                *reinterpret_cast<float2*>(out + (size_t)row * NDIM + col) = o;
            }
        }
    }
}

// ------------------------------- launch ------------------------------------
extern "C" void kernel_launch(void* const* d_in, const int* in_sizes, int n_in,
                              void* d_out, int out_size) {
    const float* x     = (const float*)d_in[0];
    const int*   q     = (const int*)d_in[1];
    const int*   zp    = (const int*)d_in[2];
    const float* scale = (const float*)d_in[3];
    const float* bias  = (const float*)d_in[4];
    float* out = (float*)d_out;

    cudaFuncSetAttribute(gemm_kernel, cudaFuncAttributeMaxDynamicSharedMemorySize, SMEM_TOTAL);

    prep_x_kernel<<<(int)(((size_t)MDIM * KDIM / 8) / 256), 256>>>(x);
    prep_w_kernel<<<(int)(((size_t)NDIM * KDIM / 8) / 256), 256>>>(q, zp);

    const int grid = (MDIM / BM) * (NDIM / BN);   // 64 * 16 = 1024
    gemm_kernel<<<grid, 256, SMEM_TOTAL>>>(bias, scale, out);
}

// round 4
// speedup vs baseline: 1.5447x; 1.2222x over previous
#include <cuda_runtime.h>
#include <cuda_fp16.h>
#include <cstdint>

// out[8192,4096] = x[8192,4096] @ W[4096,4096]^T,  W = (q - zp)*scale
// fp16 HMMA (mma.sync.m16n8k16, fp32 accum). cp.async.bulk loads from
// prep-tiled pre-swizzled scratch; register ping-pong pipelines LDSM under MMA.
#define MDIM 8192
#define KDIM 4096
#define NDIM 4096

static constexpr int BM = 128, BN = 256, BK = 32;
static constexpr int A_BLK = BM * BK * 2;     // 8192 B per (m-tile, k-chunk)
static constexpr int B_BLK = BN * BK * 2;     // 16384 B
static constexpr int STAGE = A_BLK + B_BLK;   // 24576
static constexpr int ST = 4;
static constexpr int KT = KDIM / BK;          // 128
static constexpr int SMEM_TOTAL = 1024 + ST * STAGE;  // 99328

// tiled+swizzled scratch: A: [64 m-tiles][128 kt][8KB], B: [16 n-tiles][128 kt][16KB]
__device__ uint4 g_xa[(size_t)MDIM * KDIM * 2 / 16];
__device__ uint4 g_wb[(size_t)NDIM * KDIM * 2 / 16];

__device__ __forceinline__ uint32_t smem_to_u32(const void* p) {
    uint32_t a;
    asm("{ .reg .u64 t; cvta.to.shared.u64 t, %1; cvt.u32.u64 %0, t; }"
        : "=r"(a) : "l"(p));
    return a;
}

#define MBARRIER_INIT(addr, cnt) \
    asm volatile("mbarrier.init.shared.b64 [%0], %1;" :: "r"((uint32_t)(addr)), "r"((uint32_t)(cnt)) : "memory")
#define MBARRIER_ARRIVE(addr) \
    asm volatile("mbarrier.arrive.shared.b64 _, [%0];" :: "r"((uint32_t)(addr)) : "memory")
#define MBARRIER_EXPECT_TX(addr, bytes) \
    asm volatile("mbarrier.arrive.expect_tx.shared.b64 _, [%0], %1;" :: "r"((uint32_t)(addr)), "r"((uint32_t)(bytes)) : "memory")
#define MBARRIER_WAIT_PARITY(mbar_smem_addr, phase_parity) do { \
    uint32_t _mbar = (uint32_t)(mbar_smem_addr); \
    uint32_t _parity = (uint32_t)(phase_parity); \
    uint32_t _done; \
    asm volatile( \
        "{\n\t.reg .pred p;\n\t" \
        "mbarrier.try_wait.parity.acquire.cta.shared::cta.b64 p, [%1], %2;\n\t" \
        "selp.b32 %0, 1, 0, p;\n\t}" \
        : "=r"(_done) : "r"(_mbar), "r"(_parity) : "memory"); \
    if (!_done) { \
        asm volatile( \
            "{\n\t.reg .pred P1;\n\t" \
            "WAIT_LOOP_%=:\n\t" \
            "mbarrier.try_wait.parity.acquire.cta.shared::cta.b64 P1, [%0], %1, 0x989680;\n\t" \
            "@P1 bra.uni WAIT_DONE_%=;\n\t" \
            "bra.uni WAIT_LOOP_%=;\n\t" \
            "WAIT_DONE_%=:\n\t}" \
            :: "r"(_mbar), "r"(_parity) : "memory"); \
    } \
} while(0)

#define BULK_G2S(dst, src, bytes, mbar) \
    asm volatile("cp.async.bulk.shared::cluster.global.mbarrier::complete_tx::bytes [%0], [%1], %2, [%3];" \
        :: "r"((uint32_t)(dst)), "l"(src), "r"((uint32_t)(bytes)), "r"((uint32_t)(mbar)) : "memory")

#define LDMATRIX_X4(r0, r1, r2, r3, addr) \
    asm volatile("ldmatrix.sync.aligned.m8n8.x4.shared.b16 {%0,%1,%2,%3}, [%4];" \
        : "=r"(r0), "=r"(r1), "=r"(r2), "=r"(r3) : "r"(addr))

#define MMA_16816(c, a0, a1, a2, a3, b0, b1) \
    asm volatile("mma.sync.aligned.m16n8k16.row.col.f32.f16.f16.f32 " \
        "{%0,%1,%2,%3}, {%4,%5,%6,%7}, {%8,%9}, {%0,%1,%2,%3};" \
        : "+f"((c)[0]), "+f"((c)[1]), "+f"((c)[2]), "+f"((c)[3]) \
        : "r"(a0), "r"(a1), "r"(a2), "r"(a3), "r"(b0), "r"(b1))

// ------------------------------- prep kernels ------------------------------
// element (r, kc): byte off = (r>>1)*128 + unit*16, unit = ((r&1)*4+kc8)^((r>>1)&7)
__device__ __forceinline__ uint32_t swz_off(int r, int kc8) {
    uint32_t unit = (uint32_t)(((r & 1) * 4 + kc8) ^ ((r >> 1) & 7));
    return (uint32_t)((r >> 1) * 128) + unit * 16;
}

__global__ void __launch_bounds__(256) prep_x_kernel(const float* __restrict__ x) {
    size_t t = (size_t)blockIdx.x * blockDim.x + threadIdx.x;  // one 16B out unit
    int m = (int)(t >> 9);
    int k = ((int)t & 511) * 8;
    const float4* src = reinterpret_cast<const float4*>(x + (size_t)m * KDIM + k);
    float4 v0 = src[0], v1 = src[1];
    __half2 h0 = __floats2half2_rn(v0.x, v0.y);
    __half2 h1 = __floats2half2_rn(v0.z, v0.w);
    __half2 h2 = __floats2half2_rn(v1.x, v1.y);
    __half2 h3 = __floats2half2_rn(v1.z, v1.w);
    uint4 o;
    o.x = *reinterpret_cast<uint32_t*>(&h0);
    o.y = *reinterpret_cast<uint32_t*>(&h1);
    o.z = *reinterpret_cast<uint32_t*>(&h2);
    o.w = *reinterpret_cast<uint32_t*>(&h3);
    int mt = m >> 7, r = m & 127, kt = k >> 5, kc8 = (k & 31) >> 3;
    size_t dst = ((size_t)(mt * KT + kt) * A_BLK + swz_off(r, kc8)) >> 4;
    g_xa[dst] = o;
}

__global__ void __launch_bounds__(256) prep_w_kernel(const int* __restrict__ q,
                                                     const int* __restrict__ zp) {
    int z = __ldg(zp);
    size_t t = (size_t)blockIdx.x * blockDim.x + threadIdx.x;
    int n = (int)(t >> 9);
    int k = ((int)t & 511) * 8;
    const int4* src = reinterpret_cast<const int4*>(q + (size_t)n * KDIM + k);
    int4 q0 = src[0], q1 = src[1];
    __half2 h0 = __floats2half2_rn((float)(q0.x - z), (float)(q0.y - z));
    __half2 h1 = __floats2half2_rn((float)(q0.z - z), (float)(q0.w - z));
    __half2 h2 = __floats2half2_rn((float)(q1.x - z), (float)(q1.y - z));
    __half2 h3 = __floats2half2_rn((float)(q1.z - z), (float)(q1.w - z));
    uint4 o;
    o.x = *reinterpret_cast<uint32_t*>(&h0);
    o.y = *reinterpret_cast<uint32_t*>(&h1);
    o.z = *reinterpret_cast<uint32_t*>(&h2);
    o.w = *reinterpret_cast<uint32_t*>(&h3);
    int nt = n >> 8, r = n & 255, kt = k >> 5, kc8 = (k & 31) >> 3;
    size_t dst = ((size_t)(nt * KT + kt) * B_BLK + swz_off(r, kc8)) >> 4;
    g_wb[dst] = o;
}

// ------------------------------- GEMM --------------------------------------
// CTA 128x256, K-chunk 32. 8 warps: 2(M) x 4(N), warp tile 64x64.
// Register ping-pong: fragment buffer f^1 is filled while MMAs consume f.
__global__ void __launch_bounds__(256, 1)
gemm_kernel(const float* __restrict__ bias,
            const float* __restrict__ wscale,
            float* __restrict__ out) {
    extern __shared__ char smem[];
    const uint32_t sbase = smem_to_u32(smem);
    const int tid = threadIdx.x;
    const int lane = tid & 31;
    const int wid = tid >> 5;
    const int warp_m = wid & 1;
    const int warp_n = wid >> 1;

    // CTA swizzle: groups of 8 M-tiles sweep all 16 N-tiles
    int bid = blockIdx.x;
    int grp = bid >> 7;
    int rr = bid & 127;
    const int mt = grp * 8 + (rr & 7);
    const int nt = rr >> 3;
    const int m0 = mt * BM, n0 = nt * BN;

    const uint32_t fullb = sbase, emptyb = sbase + 128;
    if (tid == 0) {
        #pragma unroll
        for (int s = 0; s < ST; s++) {
            MBARRIER_INIT(fullb + 16 * s, 1);
            MBARRIER_INIT(emptyb + 16 * s, 8);
        }
    }
    __syncthreads();

    const char* srcA = (const char*)g_xa + (size_t)mt * KT * A_BLK;
    const char* srcB = (const char*)g_wb + (size_t)nt * KT * B_BLK;

    if (tid == 0) {
        #pragma unroll
        for (int j = 0; j < 3; j++) {
            MBARRIER_EXPECT_TX(fullb + 16 * j, STAGE);
            BULK_G2S(sbase + 1024 + j * STAGE, srcA + (size_t)j * A_BLK, A_BLK, fullb + 16 * j);
            BULK_G2S(sbase + 1024 + j * STAGE + A_BLK, srcB + (size_t)j * B_BLK, B_BLK, fullb + 16 * j);
        }
    }

    // per-lane ldmatrix offsets
    const int rin = ((lane >> 3) & 1) * 8 + (lane & 7);
    const int kh = lane >> 4;
    const int xr = (rin >> 1) & 7;
    const int rb = (rin >> 1) * 128;
    const uint32_t off_ks0 = (uint32_t)(rb + ((((rin & 1) * 4) + kh) ^ xr) * 16);
    const uint32_t off_ks1 = (uint32_t)(rb + ((((rin & 1) * 4) + 2 + kh) ^ xr) * 16);
    const uint32_t aW = (uint32_t)(warp_m * 4096);
    const uint32_t bW = (uint32_t)(A_BLK + warp_n * 4096);

    uint32_t a[2][4][4], b[2][4][4];
    float acc[4][8][4];
    #pragma unroll
    for (int i = 0; i < 4; i++)
        #pragma unroll
        for (int j = 0; j < 8; j++)
            #pragma unroll
            for (int c = 0; c < 4; c++) acc[i][j][c] = 0.f;

    // prologue: wait stage 0, load frag(kt=0, ks=0) into buf 0
    MBARRIER_WAIT_PARITY(fullb, 0);
    {
        const uint32_t sa = sbase + 1024;
        #pragma unroll
        for (int mi = 0; mi < 4; mi++)
            LDMATRIX_X4(a[0][mi][0], a[0][mi][1], a[0][mi][2], a[0][mi][3],
                        sa + aW + mi * 1024 + off_ks0);
        #pragma unroll
        for (int nj = 0; nj < 4; nj++)
            LDMATRIX_X4(b[0][nj][0], b[0][nj][1], b[0][nj][2], b[0][nj][3],
                        sa + bW + nj * 1024 + off_ks0);
    }

    int cur = 0;
    #pragma unroll 1
    for (int kt = 0; kt < KT; kt++) {
        const int s = kt & 3;
        const uint32_t sa = sbase + 1024 + s * STAGE;

        // producer: refill stage (kt+3)&3 with chunk kt+3
        if (tid == 0) {
            int j = kt + 3;
            if (j < KT) {
                int sj = j & 3;
                if (j >= 4) MBARRIER_WAIT_PARITY(emptyb + 16 * sj, ((j - 4) >> 2) & 1);
                MBARRIER_EXPECT_TX(fullb + 16 * sj, STAGE);
                BULK_G2S(sbase + 1024 + sj * STAGE, srcA + (size_t)j * A_BLK, A_BLK, fullb + 16 * sj);
                BULK_G2S(sbase + 1024 + sj * STAGE + A_BLK, srcB + (size_t)j * B_BLK, B_BLK, fullb + 16 * sj);
            }
        }

        // ---- ks = 0: prefetch ks=1 frags (same stage), then MMA on cur ----
        {
            const int nb = cur ^ 1;
            #pragma unroll
            for (int mi = 0; mi < 4; mi++)
                LDMATRIX_X4(a[nb][mi][0], a[nb][mi][1], a[nb][mi][2], a[nb][mi][3],
                            sa + aW + mi * 1024 + off_ks1);
            #pragma unroll
            for (int nj = 0; nj < 4; nj++)
                LDMATRIX_X4(b[nb][nj][0], b[nb][nj][1], b[nb][nj][2], b[nb][nj][3],
                            sa + bW + nj * 1024 + off_ks1);
            // stage s fully read by this warp
            if (lane == 0) MBARRIER_ARRIVE(emptyb + 16 * s);
            #pragma unroll
            for (int mi = 0; mi < 4; mi++)
                #pragma unroll
                for (int v = 0; v < 8; v++) {
                    int nj = v >> 1, tb = v & 1;
                    MMA_16816(acc[mi][v],
                              a[cur][mi][0], a[cur][mi][1], a[cur][mi][2], a[cur][mi][3],
                              b[cur][nj][tb], b[cur][nj][tb + 2]);
                }
            cur = nb;
        }

        // ---- ks = 1: wait next stage + prefetch (kt+1, ks=0), MMA on cur ----
        {
            const int nb = cur ^ 1;
            if (kt + 1 < KT) {
                const int s2 = (kt + 1) & 3;
                MBARRIER_WAIT_PARITY(fullb + 16 * s2, ((kt + 1) >> 2) & 1);
                const uint32_t sa2 = sbase + 1024 + s2 * STAGE;
                #pragma unroll
                for (int mi = 0; mi < 4; mi++)
                    LDMATRIX_X4(a[nb][mi][0], a[nb][mi][1], a[nb][mi][2], a[nb][mi][3],
                                sa2 + aW + mi * 1024 + off_ks0);
                #pragma unroll
                for (int nj = 0; nj < 4; nj++)
                    LDMATRIX_X4(b[nb][nj][0], b[nb][nj][1], b[nb][nj][2], b[nb][nj][3],
                                sa2 + bW + nj * 1024 + off_ks0);
            }
            #pragma unroll
            for (int mi = 0; mi < 4; mi++)
                #pragma unroll
                for (int v = 0; v < 8; v++) {
                    int nj = v >> 1, tb = v & 1;
                    MMA_16816(acc[mi][v],
                              a[cur][mi][0], a[cur][mi][1], a[cur][mi][2], a[cur][mi][3],
                              b[cur][nj][tb], b[cur][nj][tb + 2]);
                }
            cur = nb;
        }
    }

    // epilogue: scale + bias, float2 stores
    const float scale = __ldg(wscale);
    const int g = lane >> 2, tg = lane & 3;
    #pragma unroll
    for (int mi = 0; mi < 4; mi++) {
        #pragma unroll
        for (int v = 0; v < 8; v++) {
            int col = n0 + warp_n * 64 + v * 8 + tg * 2;
            float2 bb = *reinterpret_cast<const float2*>(bias + col);
            #pragma unroll
            for (int rh = 0; rh < 2; rh++) {
                int row = m0 + warp_m * 64 + mi * 16 + g + rh * 8;
                float2 o;
                o.x = acc[mi][v][rh * 2 + 0] * scale + bb.x;
                o.y = acc[mi][v][rh * 2 + 1] * scale + bb.y;
                *reinterpret_cast<float2*>(out + (size_t)row * NDIM + col) = o;
            }
        }
    }
}

// ------------------------------- launch ------------------------------------
extern "C" void kernel_launch(void* const* d_in, const int* in_sizes, int n_in,
                              void* d_out, int out_size) {
    const float* x     = (const float*)d_in[0];
    const int*   q     = (const int*)d_in[1];
    const int*   zp    = (const int*)d_in[2];
    const float* scale = (const float*)d_in[3];
    const float* bias  = (const float*)d_in[4];
    float* out = (float*)d_out;

    cudaFuncSetAttribute(gemm_kernel, cudaFuncAttributeMaxDynamicSharedMemorySize, SMEM_TOTAL);

    prep_x_kernel<<<(int)(((size_t)MDIM * KDIM / 8) / 256), 256>>>(x);
    prep_w_kernel<<<(int)(((size_t)NDIM * KDIM / 8) / 256), 256>>>(q, zp);

    const int grid = (MDIM / BM) * (NDIM / BN);   // 64 * 16 = 1024
    gemm_kernel<<<grid, 256, SMEM_TOTAL>>>(bias, scale, out);
}

// round 6
// speedup vs baseline: 1.6204x; 1.0490x over previous
#include <cuda_runtime.h>
#include <cuda_fp16.h>
#include <cstdint>

// out[8192,4096] = x[8192,4096] @ W[4096,4096]^T,  W = (q - zp)*scale
// fp16 HMMA (mma.sync.m16n8k16, fp32 accum). cp.async.bulk loads from
// prep-tiled pre-swizzled scratch; register ping-pong; BK=64 to amortize
// per-iteration barrier/wait overhead over 2048 tensor cycles.
#define MDIM 8192
#define KDIM 4096
#define NDIM 4096

static constexpr int BM = 128, BN = 256, BK = 64;
static constexpr int A_BLK = BM * BK * 2;     // 16384 B per (m-tile, k-chunk)
static constexpr int B_BLK = BN * BK * 2;     // 32768 B
static constexpr int STAGE = A_BLK + B_BLK;   // 49152
static constexpr int ST = 4;
static constexpr int KT = KDIM / BK;          // 64
static constexpr int SMEM_TOTAL = 1024 + ST * STAGE;  // 197632

// tiled+swizzled scratch: A: [64 mt][64 kt][16KB], B: [16 nt][64 kt][32KB]
// row r holds its 128B K-slice; 16B unit u at offset r*128 + (u^(r&7))*16.
__device__ uint4 g_xa[(size_t)MDIM * KDIM * 2 / 16];
__device__ uint4 g_wb[(size_t)NDIM * KDIM * 2 / 16];

__device__ __forceinline__ uint32_t smem_to_u32(const void* p) {
    uint32_t a;
    asm("{ .reg .u64 t; cvta.to.shared.u64 t, %1; cvt.u32.u64 %0, t; }"
        : "=r"(a) : "l"(p));
    return a;
}

#define MBARRIER_INIT(addr, cnt) \
    asm volatile("mbarrier.init.shared.b64 [%0], %1;" :: "r"((uint32_t)(addr)), "r"((uint32_t)(cnt)) : "memory")
#define MBARRIER_ARRIVE(addr) \
    asm volatile("mbarrier.arrive.shared.b64 _, [%0];" :: "r"((uint32_t)(addr)) : "memory")
#define MBARRIER_EXPECT_TX(addr, bytes) \
    asm volatile("mbarrier.arrive.expect_tx.shared.b64 _, [%0], %1;" :: "r"((uint32_t)(addr)), "r"((uint32_t)(bytes)) : "memory")
#define MBARRIER_WAIT_PARITY(mbar_smem_addr, phase_parity) do { \
    uint32_t _mbar = (uint32_t)(mbar_smem_addr); \
    uint32_t _parity = (uint32_t)(phase_parity); \
    uint32_t _done; \
    asm volatile( \
        "{\n\t.reg .pred p;\n\t" \
        "mbarrier.try_wait.parity.acquire.cta.shared::cta.b64 p, [%1], %2;\n\t" \
        "selp.b32 %0, 1, 0, p;\n\t}" \
        : "=r"(_done) : "r"(_mbar), "r"(_parity) : "memory"); \
    if (!_done) { \
        asm volatile( \
            "{\n\t.reg .pred P1;\n\t" \
            "WAIT_LOOP_%=:\n\t" \
            "mbarrier.try_wait.parity.acquire.cta.shared::cta.b64 P1, [%0], %1, 0x989680;\n\t" \
            "@P1 bra.uni WAIT_DONE_%=;\n\t" \
            "bra.uni WAIT_LOOP_%=;\n\t" \
            "WAIT_DONE_%=:\n\t}" \
            :: "r"(_mbar), "r"(_parity) : "memory"); \
    } \
} while(0)

#define BULK_G2S(dst, src, bytes, mbar) \
    asm volatile("cp.async.bulk.shared::cluster.global.mbarrier::complete_tx::bytes [%0], [%1], %2, [%3];" \
        :: "r"((uint32_t)(dst)), "l"(src), "r"((uint32_t)(bytes)), "r"((uint32_t)(mbar)) : "memory")

#define LDMATRIX_X4(r0, r1, r2, r3, addr) \
    asm volatile("ldmatrix.sync.aligned.m8n8.x4.shared.b16 {%0,%1,%2,%3}, [%4];" \
        : "=r"(r0), "=r"(r1), "=r"(r2), "=r"(r3) : "r"(addr))

#define MMA_16816(c, a0, a1, a2, a3, b0, b1) \
    asm volatile("mma.sync.aligned.m16n8k16.row.col.f32.f16.f16.f32 " \
        "{%0,%1,%2,%3}, {%4,%5,%6,%7}, {%8,%9}, {%0,%1,%2,%3};" \
        : "+f"((c)[0]), "+f"((c)[1]), "+f"((c)[2]), "+f"((c)[3]) \
        : "r"(a0), "r"(a1), "r"(a2), "r"(a3), "r"(b0), "r"(b1))

// ------------------------------- prep kernels ------------------------------
__global__ void __launch_bounds__(256) prep_x_kernel(const float* __restrict__ x) {
    size_t t = (size_t)blockIdx.x * blockDim.x + threadIdx.x;  // one 16B out unit
    int m = (int)(t >> 9);              // 512 units per 4096-k row
    int k = ((int)t & 511) * 8;
    const float4* src = reinterpret_cast<const float4*>(x + (size_t)m * KDIM + k);
    float4 v0 = src[0], v1 = src[1];
    __half2 h0 = __floats2half2_rn(v0.x, v0.y);
    __half2 h1 = __floats2half2_rn(v0.z, v0.w);
    __half2 h2 = __floats2half2_rn(v1.x, v1.y);
    __half2 h3 = __floats2half2_rn(v1.z, v1.w);
    uint4 o;
    o.x = *reinterpret_cast<uint32_t*>(&h0);
    o.y = *reinterpret_cast<uint32_t*>(&h1);
    o.z = *reinterpret_cast<uint32_t*>(&h2);
    o.w = *reinterpret_cast<uint32_t*>(&h3);
    int mt = m >> 7, r = m & 127, kt = k >> 6, kc8 = (k & 63) >> 3;
    uint32_t off = (uint32_t)r * 128 + (uint32_t)((kc8 ^ (r & 7)) * 16);
    g_xa[((size_t)(mt * KT + kt) * A_BLK + off) >> 4] = o;
}

__global__ void __launch_bounds__(256) prep_w_kernel(const int* __restrict__ q,
                                                     const int* __restrict__ zp) {
    int z = __ldg(zp);
    size_t t = (size_t)blockIdx.x * blockDim.x + threadIdx.x;
    int n = (int)(t >> 9);
    int k = ((int)t & 511) * 8;
    const int4* src = reinterpret_cast<const int4*>(q + (size_t)n * KDIM + k);
    int4 q0 = src[0], q1 = src[1];
    __half2 h0 = __floats2half2_rn((float)(q0.x - z), (float)(q0.y - z));
    __half2 h1 = __floats2half2_rn((float)(q0.z - z), (float)(q0.w - z));
    __half2 h2 = __floats2half2_rn((float)(q1.x - z), (float)(q1.y - z));
    __half2 h3 = __floats2half2_rn((float)(q1.z - z), (float)(q1.w - z));
    uint4 o;
    o.x = *reinterpret_cast<uint32_t*>(&h0);
    o.y = *reinterpret_cast<uint32_t*>(&h1);
    o.z = *reinterpret_cast<uint32_t*>(&h2);
    o.w = *reinterpret_cast<uint32_t*>(&h3);
    int nt = n >> 8, r = n & 255, kt = k >> 6, kc8 = (k & 63) >> 3;
    uint32_t off = (uint32_t)r * 128 + (uint32_t)((kc8 ^ (r & 7)) * 16);
    g_wb[((size_t)(nt * KT + kt) * B_BLK + off) >> 4] = o;
}

// ------------------------------- GEMM --------------------------------------
// CTA 128x256, K-chunk 64. 8 warps: 2(M) x 4(N), warp tile 64x64.
__global__ void __launch_bounds__(256, 1)
gemm_kernel(const float* __restrict__ bias,
            const float* __restrict__ wscale,
            float* __restrict__ out) {
    extern __shared__ char smem[];
    const uint32_t sbase = smem_to_u32(smem);
    const int tid = threadIdx.x;
    const int lane = tid & 31;
    const int wid = tid >> 5;
    const int warp_m = wid & 1;
    const int warp_n = wid >> 1;

    // CTA swizzle: groups of 8 M-tiles sweep all 16 N-tiles
    int bid = blockIdx.x;
    int grp = bid >> 7;
    int rr = bid & 127;
    const int mt = grp * 8 + (rr & 7);
    const int nt = rr >> 3;
    const int m0 = mt * BM, n0 = nt * BN;

    const uint32_t fullb = sbase, emptyb = sbase + 128;
    if (tid == 0) {
        #pragma unroll
        for (int s = 0; s < ST; s++) {
            MBARRIER_INIT(fullb + 16 * s, 1);
            MBARRIER_INIT(emptyb + 16 * s, 8);
        }
    }
    __syncthreads();

    const char* srcA = (const char*)g_xa + (size_t)mt * KT * A_BLK;
    const char* srcB = (const char*)g_wb + (size_t)nt * KT * B_BLK;

    if (tid == 0) {
        #pragma unroll
        for (int j = 0; j < 3; j++) {
            MBARRIER_EXPECT_TX(fullb + 16 * j, STAGE);
            BULK_G2S(sbase + 1024 + j * STAGE, srcA + (size_t)j * A_BLK, A_BLK, fullb + 16 * j);
            BULK_G2S(sbase + 1024 + j * STAGE + A_BLK, srcB + (size_t)j * B_BLK, B_BLK, fullb + 16 * j);
        }
    }

    // per-lane ldmatrix components. Row pitch = 128B; lane row-in-16 = rin.
    const int rin = ((lane >> 3) & 1) * 8 + (lane & 7);   // 0..15
    const int kh = lane >> 4;                              // k-half within k16
    const int xr = rin & 7;
    uint32_t off_k[4];
    #pragma unroll
    for (int ks = 0; ks < 4; ks++)
        off_k[ks] = (uint32_t)(((ks * 2 + kh) ^ xr) * 16);
    const uint32_t aBase = (uint32_t)((warp_m * 64 + rin) * 128);
    const uint32_t bBase = (uint32_t)(A_BLK + (warp_n * 64 + rin) * 128);

    uint32_t a[2][4][4], b[2][4][4];
    float acc[4][8][4];
    #pragma unroll
    for (int i = 0; i < 4; i++)
        #pragma unroll
        for (int j = 0; j < 8; j++)
            #pragma unroll
            for (int c = 0; c < 4; c++) acc[i][j][c] = 0.f;

    // fragment loader: fills buffer d from stage base sa with k-step offset ko
    auto load_frags = [&](int d, uint32_t sa, uint32_t ko) {
        #pragma unroll
        for (int mi = 0; mi < 4; mi++)
            LDMATRIX_X4(a[d][mi][0], a[d][mi][1], a[d][mi][2], a[d][mi][3],
                        sa + aBase + mi * 2048 + ko);
        #pragma unroll
        for (int nj = 0; nj < 4; nj++)
            LDMATRIX_X4(b[d][nj][0], b[d][nj][1], b[d][nj][2], b[d][nj][3],
                        sa + bBase + nj * 2048 + ko);
    };
    auto mma_block = [&](int d) {
        #pragma unroll
        for (int mi = 0; mi < 4; mi++)
            #pragma unroll
            for (int v = 0; v < 8; v++) {
                int nj = v >> 1, tb = v & 1;
                MMA_16816(acc[mi][v],
                          a[d][mi][0], a[d][mi][1], a[d][mi][2], a[d][mi][3],
                          b[d][nj][tb], b[d][nj][tb + 2]);
            }
    };

    // prologue: wait stage 0, load (kt=0, ks=0) into buf 0
    MBARRIER_WAIT_PARITY(fullb, 0);
    load_frags(0, sbase + 1024, off_k[0]);

    int cur = 0;
    #pragma unroll 1
    for (int kt = 0; kt < KT; kt++) {
        const int s = kt & 3;
        const uint32_t sa = sbase + 1024 + s * STAGE;

        // ks=0: prefetch ks1, MMA
        load_frags(cur ^ 1, sa, off_k[1]);
        mma_block(cur);
        cur ^= 1;

        // producer: refill stage (kt+3)&3; warp 0's empty-wait has slack now
        if (tid == 0) {
            int j = kt + 3;
            if (j < KT) {
                int sj = j & 3;
                if (j >= 4) MBARRIER_WAIT_PARITY(emptyb + 16 * sj, ((j - 4) >> 2) & 1);
                MBARRIER_EXPECT_TX(fullb + 16 * sj, STAGE);
                BULK_G2S(sbase + 1024 + sj * STAGE, srcA + (size_t)j * A_BLK, A_BLK, fullb + 16 * sj);
                BULK_G2S(sbase + 1024 + sj * STAGE + A_BLK, srcB + (size_t)j * B_BLK, B_BLK, fullb + 16 * sj);
            }
        }

        // ks=1: prefetch ks2, MMA
        load_frags(cur ^ 1, sa, off_k[2]);
        mma_block(cur);
        cur ^= 1;

        // ks=2: prefetch ks3, arrive empty (stage fully read after this), MMA
        load_frags(cur ^ 1, sa, off_k[3]);
        if (lane == 0) MBARRIER_ARRIVE(emptyb + 16 * s);
        mma_block(cur);
        cur ^= 1;

        // ks=3: wait next stage, prefetch (kt+1, ks=0), MMA
        if (kt + 1 < KT) {
            const int s2 = (kt + 1) & 3;
            MBARRIER_WAIT_PARITY(fullb + 16 * s2, ((kt + 1) >> 2) & 1);
            load_frags(cur ^ 1, sbase + 1024 + s2 * STAGE, off_k[0]);
        }
        mma_block(cur);
        cur ^= 1;
    }

    // epilogue: scale + bias, float2 stores
    const float scale = __ldg(wscale);
    const int g = lane >> 2, tg = lane & 3;
    #pragma unroll
    for (int mi = 0; mi < 4; mi++) {
        #pragma unroll
        for (int v = 0; v < 8; v++) {
            int col = n0 + warp_n * 64 + v * 8 + tg * 2;
            float2 bb = *reinterpret_cast<const float2*>(bias + col);
            #pragma unroll
            for (int rh = 0; rh < 2; rh++) {
                int row = m0 + warp_m * 64 + mi * 16 + g + rh * 8;
                float2 o;
                o.x = acc[mi][v][rh * 2 + 0] * scale + bb.x;
                o.y = acc[mi][v][rh * 2 + 1] * scale + bb.y;
                *reinterpret_cast<float2*>(out + (size_t)row * NDIM + col) = o;
            }
        }
    }
}

// ------------------------------- launch ------------------------------------
extern "C" void kernel_launch(void* const* d_in, const int* in_sizes, int n_in,
                              void* d_out, int out_size) {
    const float* x     = (const float*)d_in[0];
    const int*   q     = (const int*)d_in[1];
    const int*   zp    = (const int*)d_in[2];
    const float* scale = (const float*)d_in[3];
    const float* bias  = (const float*)d_in[4];
    float* out = (float*)d_out;

    cudaFuncSetAttribute(gemm_kernel, cudaFuncAttributeMaxDynamicSharedMemorySize, SMEM_TOTAL);

    prep_x_kernel<<<(int)(((size_t)MDIM * KDIM / 8) / 256), 256>>>(x);
    prep_w_kernel<<<(int)(((size_t)NDIM * KDIM / 8) / 256), 256>>>(q, zp);

    const int grid = (MDIM / BM) * (NDIM / BN);   // 64 * 16 = 1024
    gemm_kernel<<<grid, 256, SMEM_TOTAL>>>(bias, scale, out);
}

// round 7
// speedup vs baseline: 1.6297x; 1.0057x over previous
#include <cuda_runtime.h>
#include <cuda_fp16.h>
#include <cstdint>

// out[8192,4096] = x[8192,4096] @ W[4096,4096]^T,  W = (q - zp)*scale
// fp16 HMMA (mma.sync.m16n8k16, fp32 accum). cp.async.bulk loads from
// prep-tiled pre-swizzled scratch; register ping-pong; BK=64; producer
// round-robins across warps so no single warp is the permanent straggler.
#define MDIM 8192
#define KDIM 4096
#define NDIM 4096

static constexpr int BM = 128, BN = 256, BK = 64;
static constexpr int A_BLK = BM * BK * 2;     // 16384 B per (m-tile, k-chunk)
static constexpr int B_BLK = BN * BK * 2;     // 32768 B
static constexpr int STAGE = A_BLK + B_BLK;   // 49152
static constexpr int ST = 4;
static constexpr int KT = KDIM / BK;          // 64
static constexpr int SMEM_TOTAL = 1024 + ST * STAGE;  // 197632

// tiled+swizzled scratch: A: [64 mt][64 kt][16KB], B: [16 nt][64 kt][32KB]
// row r holds its 128B K-slice; 16B unit u at offset r*128 + (u^(r&7))*16.
__device__ uint4 g_xa[(size_t)MDIM * KDIM * 2 / 16];
__device__ uint4 g_wb[(size_t)NDIM * KDIM * 2 / 16];

__device__ __forceinline__ uint32_t smem_to_u32(const void* p) {
    uint32_t a;
    asm("{ .reg .u64 t; cvta.to.shared.u64 t, %1; cvt.u32.u64 %0, t; }"
        : "=r"(a) : "l"(p));
    return a;
}

#define MBARRIER_INIT(addr, cnt) \
    asm volatile("mbarrier.init.shared.b64 [%0], %1;" :: "r"((uint32_t)(addr)), "r"((uint32_t)(cnt)) : "memory")
#define MBARRIER_ARRIVE(addr) \
    asm volatile("mbarrier.arrive.shared.b64 _, [%0];" :: "r"((uint32_t)(addr)) : "memory")
#define MBARRIER_EXPECT_TX(addr, bytes) \
    asm volatile("mbarrier.arrive.expect_tx.shared.b64 _, [%0], %1;" :: "r"((uint32_t)(addr)), "r"((uint32_t)(bytes)) : "memory")
#define MBARRIER_WAIT_PARITY(mbar_smem_addr, phase_parity) do { \
    uint32_t _mbar = (uint32_t)(mbar_smem_addr); \
    uint32_t _parity = (uint32_t)(phase_parity); \
    uint32_t _done; \
    asm volatile( \
        "{\n\t.reg .pred p;\n\t" \
        "mbarrier.try_wait.parity.acquire.cta.shared::cta.b64 p, [%1], %2;\n\t" \
        "selp.b32 %0, 1, 0, p;\n\t}" \
        : "=r"(_done) : "r"(_mbar), "r"(_parity) : "memory"); \
    if (!_done) { \
        asm volatile( \
            "{\n\t.reg .pred P1;\n\t" \
            "WAIT_LOOP_%=:\n\t" \
            "mbarrier.try_wait.parity.acquire.cta.shared::cta.b64 P1, [%0], %1, 0x989680;\n\t" \
            "@P1 bra.uni WAIT_DONE_%=;\n\t" \
            "bra.uni WAIT_LOOP_%=;\n\t" \
            "WAIT_DONE_%=:\n\t}" \
            :: "r"(_mbar), "r"(_parity) : "memory"); \
    } \
} while(0)

#define BULK_G2S(dst, src, bytes, mbar) \
    asm volatile("cp.async.bulk.shared::cluster.global.mbarrier::complete_tx::bytes [%0], [%1], %2, [%3];" \
        :: "r"((uint32_t)(dst)), "l"(src), "r"((uint32_t)(bytes)), "r"((uint32_t)(mbar)) : "memory")

#define LDMATRIX_X4(r0, r1, r2, r3, addr) \
    asm volatile("ldmatrix.sync.aligned.m8n8.x4.shared.b16 {%0,%1,%2,%3}, [%4];" \
        : "=r"(r0), "=r"(r1), "=r"(r2), "=r"(r3) : "r"(addr))

#define MMA_16816(c, a0, a1, a2, a3, b0, b1) \
    asm volatile("mma.sync.aligned.m16n8k16.row.col.f32.f16.f16.f32 " \
        "{%0,%1,%2,%3}, {%4,%5,%6,%7}, {%8,%9}, {%0,%1,%2,%3};" \
        : "+f"((c)[0]), "+f"((c)[1]), "+f"((c)[2]), "+f"((c)[3]) \
        : "r"(a0), "r"(a1), "r"(a2), "r"(a3), "r"(b0), "r"(b1))

// ------------------------------- prep kernel -------------------------------
// One launch covers both inputs: blocks [0, XBLKS) convert x, rest convert W.
static constexpr int XBLKS = (int)(((size_t)MDIM * KDIM / 8) / 256);  // 16384
static constexpr int WBLKS = (int)(((size_t)NDIM * KDIM / 8) / 256);  // 8192

__global__ void __launch_bounds__(256) prep_kernel(const float* __restrict__ x,
                                                   const int* __restrict__ q,
                                                   const int* __restrict__ zp) {
    if (blockIdx.x < XBLKS) {
        size_t t = (size_t)blockIdx.x * blockDim.x + threadIdx.x;  // one 16B unit
        int m = (int)(t >> 9);
        int k = ((int)t & 511) * 8;
        const float4* src = reinterpret_cast<const float4*>(x + (size_t)m * KDIM + k);
        float4 v0 = src[0], v1 = src[1];
        __half2 h0 = __floats2half2_rn(v0.x, v0.y);
        __half2 h1 = __floats2half2_rn(v0.z, v0.w);
        __half2 h2 = __floats2half2_rn(v1.x, v1.y);
        __half2 h3 = __floats2half2_rn(v1.z, v1.w);
        uint4 o;
        o.x = *reinterpret_cast<uint32_t*>(&h0);
        o.y = *reinterpret_cast<uint32_t*>(&h1);
        o.z = *reinterpret_cast<uint32_t*>(&h2);
        o.w = *reinterpret_cast<uint32_t*>(&h3);
        int mt = m >> 7, r = m & 127, kt = k >> 6, kc8 = (k & 63) >> 3;
        uint32_t off = (uint32_t)r * 128 + (uint32_t)((kc8 ^ (r & 7)) * 16);
        g_xa[((size_t)(mt * KT + kt) * A_BLK + off) >> 4] = o;
    } else {
        int z = __ldg(zp);
        size_t t = (size_t)(blockIdx.x - XBLKS) * blockDim.x + threadIdx.x;
        int n = (int)(t >> 9);
        int k = ((int)t & 511) * 8;
        const int4* src = reinterpret_cast<const int4*>(q + (size_t)n * KDIM + k);
        int4 q0 = src[0], q1 = src[1];
        __half2 h0 = __floats2half2_rn((float)(q0.x - z), (float)(q0.y - z));
        __half2 h1 = __floats2half2_rn((float)(q0.z - z), (float)(q0.w - z));
        __half2 h2 = __floats2half2_rn((float)(q1.x - z), (float)(q1.y - z));
        __half2 h3 = __floats2half2_rn((float)(q1.z - z), (float)(q1.w - z));
        uint4 o;
        o.x = *reinterpret_cast<uint32_t*>(&h0);
        o.y = *reinterpret_cast<uint32_t*>(&h1);
        o.z = *reinterpret_cast<uint32_t*>(&h2);
        o.w = *reinterpret_cast<uint32_t*>(&h3);
        int nt = n >> 8, r = n & 255, kt = k >> 6, kc8 = (k & 63) >> 3;
        uint32_t off = (uint32_t)r * 128 + (uint32_t)((kc8 ^ (r & 7)) * 16);
        g_wb[((size_t)(nt * KT + kt) * B_BLK + off) >> 4] = o;
    }
}

// ------------------------------- GEMM --------------------------------------
// CTA 128x256, K-chunk 64. 8 warps: 2(M) x 4(N), warp tile 64x64.
__global__ void __launch_bounds__(256, 1)
gemm_kernel(const float* __restrict__ bias,
            const float* __restrict__ wscale,
            float* __restrict__ out) {
    extern __shared__ char smem[];
    const uint32_t sbase = smem_to_u32(smem);
    const int tid = threadIdx.x;
    const int lane = tid & 31;
    const int wid = tid >> 5;
    const int warp_m = wid & 1;
    const int warp_n = wid >> 1;

    // CTA swizzle: groups of 8 M-tiles sweep all 16 N-tiles
    int bid = blockIdx.x;
    int grp = bid >> 7;
    int rr = bid & 127;
    const int mt = grp * 8 + (rr & 7);
    const int nt = rr >> 3;
    const int m0 = mt * BM, n0 = nt * BN;

    const uint32_t fullb = sbase, emptyb = sbase + 128;
    if (tid == 0) {
        #pragma unroll
        for (int s = 0; s < ST; s++) {
            MBARRIER_INIT(fullb + 16 * s, 1);
            MBARRIER_INIT(emptyb + 16 * s, 8);
        }
    }
    __syncthreads();

    const char* srcA = (const char*)g_xa + (size_t)mt * KT * A_BLK;
    const char* srcB = (const char*)g_wb + (size_t)nt * KT * B_BLK;

    if (tid == 0) {
        #pragma unroll
        for (int j = 0; j < 3; j++) {
            MBARRIER_EXPECT_TX(fullb + 16 * j, STAGE);
            BULK_G2S(sbase + 1024 + j * STAGE, srcA + (size_t)j * A_BLK, A_BLK, fullb + 16 * j);
            BULK_G2S(sbase + 1024 + j * STAGE + A_BLK, srcB + (size_t)j * B_BLK, B_BLK, fullb + 16 * j);
        }
    }

    // per-lane ldmatrix components. Row pitch = 128B; lane row-in-16 = rin.
    const int rin = ((lane >> 3) & 1) * 8 + (lane & 7);   // 0..15
    const int kh = lane >> 4;                              // k-half within k16
    const int xr = rin & 7;
    uint32_t off_k[4];
    #pragma unroll
    for (int ks = 0; ks < 4; ks++)
        off_k[ks] = (uint32_t)(((ks * 2 + kh) ^ xr) * 16);
    const uint32_t aBase = (uint32_t)((warp_m * 64 + rin) * 128);
    const uint32_t bBase = (uint32_t)(A_BLK + (warp_n * 64 + rin) * 128);

    uint32_t a[2][4][4], b[2][4][4];
    float acc[4][8][4];
    #pragma unroll
    for (int i = 0; i < 4; i++)
        #pragma unroll
        for (int j = 0; j < 8; j++)
            #pragma unroll
            for (int c = 0; c < 4; c++) acc[i][j][c] = 0.f;

    auto load_frags = [&](int d, uint32_t sa, uint32_t ko) {
        #pragma unroll
        for (int mi = 0; mi < 4; mi++)
            LDMATRIX_X4(a[d][mi][0], a[d][mi][1], a[d][mi][2], a[d][mi][3],
                        sa + aBase + mi * 2048 + ko);
        #pragma unroll
        for (int nj = 0; nj < 4; nj++)
            LDMATRIX_X4(b[d][nj][0], b[d][nj][1], b[d][nj][2], b[d][nj][3],
                        sa + bBase + nj * 2048 + ko);
    };
    auto mma_block = [&](int d) {
        #pragma unroll
        for (int mi = 0; mi < 4; mi++)
            #pragma unroll
            for (int v = 0; v < 8; v++) {
                int nj = v >> 1, tb = v & 1;
                MMA_16816(acc[mi][v],
                          a[d][mi][0], a[d][mi][1], a[d][mi][2], a[d][mi][3],
                          b[d][nj][tb], b[d][nj][tb + 2]);
            }
    };

    // prologue: wait stage 0, load (kt=0, ks=0) into buf 0
    MBARRIER_WAIT_PARITY(fullb, 0);
    load_frags(0, sbase + 1024, off_k[0]);

    int cur = 0;
    #pragma unroll 1
    for (int kt = 0; kt < KT; kt++) {
        const int s = kt & 3;
        const uint32_t sa = sbase + 1024 + s * STAGE;

        // ks=0: prefetch ks1, MMA
        load_frags(cur ^ 1, sa, off_k[1]);
        mma_block(cur);
        cur ^= 1;

        // producer: round-robin across warps — warp (kt&7), lane 0, fills
        // stage (kt+3)&3 with chunk kt+3. Amortizes the producer cost 8x.
        if (wid == (kt & 7) && lane == 0) {
            int j = kt + 3;
            if (j < KT) {
                int sj = j & 3;
                if (j >= 4) MBARRIER_WAIT_PARITY(emptyb + 16 * sj, ((j - 4) >> 2) & 1);
                MBARRIER_EXPECT_TX(fullb + 16 * sj, STAGE);
                BULK_G2S(sbase + 1024 + sj * STAGE, srcA + (size_t)j * A_BLK, A_BLK, fullb + 16 * sj);
                BULK_G2S(sbase + 1024 + sj * STAGE + A_BLK, srcB + (size_t)j * B_BLK, B_BLK, fullb + 16 * sj);
            }
        }

        // ks=1: prefetch ks2, MMA
        load_frags(cur ^ 1, sa, off_k[2]);
        mma_block(cur);
        cur ^= 1;

        // ks=2: prefetch ks3, arrive empty (stage fully read after this), MMA
        load_frags(cur ^ 1, sa, off_k[3]);
        if (lane == 0) MBARRIER_ARRIVE(emptyb + 16 * s);
        mma_block(cur);
        cur ^= 1;

        // ks=3: wait next stage, prefetch (kt+1, ks=0), MMA
        if (kt + 1 < KT) {
            const int s2 = (kt + 1) & 3;
            MBARRIER_WAIT_PARITY(fullb + 16 * s2, ((kt + 1) >> 2) & 1);
            load_frags(cur ^ 1, sbase + 1024 + s2 * STAGE, off_k[0]);
        }
        mma_block(cur);
        cur ^= 1;
    }

    // epilogue: scale + bias, float2 stores
    const float scale = __ldg(wscale);
    const int g = lane >> 2, tg = lane & 3;
    #pragma unroll
    for (int mi = 0; mi < 4; mi++) {
        #pragma unroll
        for (int v = 0; v < 8; v++) {
            int col = n0 + warp_n * 64 + v * 8 + tg * 2;
            float2 bb = *reinterpret_cast<const float2*>(bias + col);
            #pragma unroll
            for (int rh = 0; rh < 2; rh++) {
                int row = m0 + warp_m * 64 + mi * 16 + g + rh * 8;
                float2 o;
                o.x = acc[mi][v][rh * 2 + 0] * scale + bb.x;
                o.y = acc[mi][v][rh * 2 + 1] * scale + bb.y;
                *reinterpret_cast<float2*>(out + (size_t)row * NDIM + col) = o;
            }
        }
    }
}

// ------------------------------- launch ------------------------------------
extern "C" void kernel_launch(void* const* d_in, const int* in_sizes, int n_in,
                              void* d_out, int out_size) {
    const float* x     = (const float*)d_in[0];
    const int*   q     = (const int*)d_in[1];
    const int*   zp    = (const int*)d_in[2];
    const float* scale = (const float*)d_in[3];
    const float* bias  = (const float*)d_in[4];
    float* out = (float*)d_out;

    cudaFuncSetAttribute(gemm_kernel, cudaFuncAttributeMaxDynamicSharedMemorySize, SMEM_TOTAL);

    prep_kernel<<<XBLKS + WBLKS, 256>>>(x, q, zp);

    const int grid = (MDIM / BM) * (NDIM / BN);   // 64 * 16 = 1024
    gemm_kernel<<<grid, 256, SMEM_TOTAL>>>(bias, scale, out);
}